// round 3
// baseline (speedup 1.0000x reference)
#include <cuda_runtime.h>
#include <cuda_bf16.h>

#define NATOMS 512
#define NBATCH 16
#define NP 16

__global__ void __launch_bounds__(256) aev_radial_kernel(
    const float* __restrict__ dmat,   // [B, N, N]
    const float* __restrict__ zall,   // [B, N]
    float* __restrict__ out)          // [B, N, 16]
{
    constexpr float RCR        = 5.2f;
    constexpr float PI_OVER_R  = 3.14159265358979323846f / 5.2f;
    constexpr float L2E        = 1.4426950408889634f;   // log2(e)
    constexpr float C2         = -16.0f * L2E;          // coeff of d^2 (log2 domain)
    constexpr float SHF0       = 0.9f;
    constexpr float DSHF       = 0.26875f;

    const int wg   = (blockIdx.x * blockDim.x + threadIdx.x) >> 5;  // row id: b*512 + i
    const int lane = threadIdx.x & 31;
    const int b    = wg >> 9;

    const float* __restrict__ row  = dmat + (size_t)wg * NATOMS;
    const float* __restrict__ zrow = zall + (size_t)b  * NATOMS;

    float acc[NP];
#pragma unroll
    for (int p = 0; p < NP; ++p) acc[p] = 0.0f;

#pragma unroll
    for (int it = 0; it < 4; ++it) {
        const int j0 = it * 128 + lane * 4;
        const float4 dv = *reinterpret_cast<const float4*>(row  + j0);
        const float4 zv = *reinterpret_cast<const float4*>(zrow + j0);
        const float dd[4] = {dv.x, dv.y, dv.z, dv.w};
        const float zz[4] = {zv.x, zv.y, zv.z, zv.w};

#pragma unroll
        for (int e = 0; e < 4; ++e) {
            const float dj = dd[e];
            // cutoff weight; mask (d < RCR && d != 0) folded into w
            const float fc = fmaf(0.5f, __cosf(dj * PI_OVER_R), 0.5f);
            const float w  = ((dj < RCR) && (dj != 0.0f)) ? zz[e] * fc : 0.0f;
            // exp(-eta*(d-s_p)^2) in log2 domain:
            //   arg_p = C2*d^2 + (32*L2E*s_p)*d + (-16*L2E*s_p^2)
            const float x = C2 * dj * dj;
#pragma unroll
            for (int p = 0; p < NP; ++p) {
                const float sp = SHF0 + DSHF * (float)p;      // compile-time
                const float c1 = 32.0f * L2E * sp;            // compile-time
                const float c0 = -16.0f * L2E * sp * sp;      // compile-time
                const float arg = fmaf(c1, dj, x) + c0;
                float g;
                asm("ex2.approx.ftz.f32 %0, %1;" : "=f"(g) : "f"(arg));
                acc[p] = fmaf(w, g, acc[p]);
            }
        }
    }

    // warp butterfly reduction for all 16 features
#pragma unroll
    for (int p = 0; p < NP; ++p) {
#pragma unroll
        for (int off = 16; off >= 1; off >>= 1)
            acc[p] += __shfl_xor_sync(0xffffffffu, acc[p], off);
    }

    if (lane == 0) {
        float4* o = reinterpret_cast<float4*>(out + (size_t)wg * NP);
        o[0] = make_float4(acc[0],  acc[1],  acc[2],  acc[3]);
        o[1] = make_float4(acc[4],  acc[5],  acc[6],  acc[7]);
        o[2] = make_float4(acc[8],  acc[9],  acc[10], acc[11]);
        o[3] = make_float4(acc[12], acc[13], acc[14], acc[15]);
    }
}

extern "C" void kernel_launch(void* const* d_in, const int* in_sizes, int n_in,
                              void* d_out, int out_size)
{
    const float* dmat = (const float*)d_in[0];   // [16, 512, 512] float32
    const float* zall = (const float*)d_in[1];   // [16, 512] float32
    float* out        = (float*)d_out;           // [16, 512, 16] float32

    const int rows = NBATCH * NATOMS;            // 8192 warps
    const int threads = 256;                     // 8 warps / block
    const int blocks = rows / (threads / 32);    // 1024
    aev_radial_kernel<<<blocks, threads>>>(dmat, zall, out);
}

// round 5
// speedup vs baseline: 1.1215x; 1.1215x over previous
#include <cuda_runtime.h>
#include <cuda_bf16.h>

#define NATOMS 512
#define NBATCH 16
#define NP 16

__global__ void __launch_bounds__(256) aev_radial_kernel(
    const float* __restrict__ dmat,   // [B, N, N]
    const float* __restrict__ zall,   // [B, N]
    float* __restrict__ out)          // [B, N, 16]
{
    constexpr float RCR       = 5.2f;
    constexpr float PI_OVER_R = 3.14159265358979323846f / 5.2f;
    // log2-domain Gaussian constants: eta=16, shift0=0.9, dshift=0.26875
    constexpr float C2  = -23.083120654223414f;  // -eta*log2(e)
    constexpr float A1  =  12.407177351670135f;  //  2*eta*dshf*log2(e)
    constexpr float A0  =  -1.667214519364552f;  // -eta*dshf^2*log2(e)
    constexpr float RQ  =   0.09913776814937592f;// exp(-2*eta*dshf^2) = 2^(2*A0)
    constexpr float GSP =   1.075f;              // 4*dshf (group span)

    const int wg   = (blockIdx.x * blockDim.x + threadIdx.x) >> 5;  // b*512 + i
    const int lane = threadIdx.x & 31;
    const int b    = wg >> 9;

    const float* __restrict__ row  = dmat + (size_t)wg * NATOMS;
    const float* __restrict__ zrow = zall + (size_t)b  * NATOMS;

    float acc[NP];
#pragma unroll
    for (int p = 0; p < NP; ++p) acc[p] = 0.0f;

#pragma unroll
    for (int it = 0; it < 4; ++it) {
        const int j0 = it * 128 + lane * 4;
        const float4 dv = *reinterpret_cast<const float4*>(row  + j0);
        const float4 zv = *reinterpret_cast<const float4*>(zrow + j0);
        const float dd[4] = {dv.x, dv.y, dv.z, dv.w};
        const float zz[4] = {zv.x, zv.y, zv.z, zv.w};

#pragma unroll
        for (int e = 0; e < 4; ++e) {
            const float dj = dd[e];
            // cutoff weight; mask (d < RCR && d != 0) folded into w
            const float fc = fmaf(0.5f, __cosf(dj * PI_OVER_R), 0.5f);
            const float w  = ((dj < RCR) && (dj != 0.0f)) ? zz[e] * fc : 0.0f;
            const float u0 = dj - 0.9f;   // offset from first shift

            // 4 groups of 4 shifts; each group anchors 2 ex2's, then a
            // 3-step multiplicative recurrence: g<-g*q, q<-q*RQ.
#pragma unroll
            for (int k = 0; k < 4; ++k) {
                const float uk = u0 - (float)k * GSP;     // imm
                const float ag = (C2 * uk) * uk;          // -eta*uk^2 * log2e
                const float aq = fmaf(A1, uk, A0);        // log2 of step ratio
                float g, q;
                asm("ex2.approx.ftz.f32 %0, %1;" : "=f"(g) : "f"(ag));
                asm("ex2.approx.ftz.f32 %0, %1;" : "=f"(q) : "f"(aq));

                acc[4*k + 0] = fmaf(w, g, acc[4*k + 0]);
                g *= q; q *= RQ;
                acc[4*k + 1] = fmaf(w, g, acc[4*k + 1]);
                g *= q; q *= RQ;
                acc[4*k + 2] = fmaf(w, g, acc[4*k + 2]);
                g *= q;
                acc[4*k + 3] = fmaf(w, g, acc[4*k + 3]);
            }
        }
    }

    // warp butterfly reduction for all 16 features
#pragma unroll
    for (int p = 0; p < NP; ++p) {
#pragma unroll
        for (int off = 16; off >= 1; off >>= 1)
            acc[p] += __shfl_xor_sync(0xffffffffu, acc[p], off);
    }

    if (lane == 0) {
        float4* o = reinterpret_cast<float4*>(out + (size_t)wg * NP);
        o[0] = make_float4(acc[0],  acc[1],  acc[2],  acc[3]);
        o[1] = make_float4(acc[4],  acc[5],  acc[6],  acc[7]);
        o[2] = make_float4(acc[8],  acc[9],  acc[10], acc[11]);
        o[3] = make_float4(acc[12], acc[13], acc[14], acc[15]);
    }
}

extern "C" void kernel_launch(void* const* d_in, const int* in_sizes, int n_in,
                              void* d_out, int out_size)
{
    const float* dmat = (const float*)d_in[0];   // [16, 512, 512] float32
    const float* zall = (const float*)d_in[1];   // [16, 512] float32
    float* out        = (float*)d_out;           // [16, 512, 16] float32

    const int rows = NBATCH * NATOMS;            // 8192 warps
    const int threads = 256;                     // 8 warps / block
    const int blocks = rows / (threads / 32);    // 1024
    aev_radial_kernel<<<blocks, threads>>>(dmat, zall, out);
}